// round 7
// baseline (speedup 1.0000x reference)
#include <cuda_runtime.h>
#include <cstdint>

// Problem constants
#define C_    32
#define S_    9
#define H_    192
#define W_    256
#define G_    8
#define NSRC  8

#define WS    (W_*S_)        // 2304
#define HWS   (H_*WS)        // 442368
#define CHWS  (C_*HWS)       // 14155776
#define HWS4  (HWS>>2)       // 110592
#define CHWS4 (CHWS>>2)      // 3538944

// attention scratch: att[h][w][s]
__device__ float attG[H_ * W_ * S_];

// ---------------------------------------------------------------------------
// cp.async helpers
// ---------------------------------------------------------------------------
__device__ __forceinline__ void cp16(float* dst, const float4* src) {
    uint32_t s = (uint32_t)__cvta_generic_to_shared(dst);
    asm volatile("cp.async.cg.shared.global [%0], [%1], 16;\n" :: "r"(s), "l"(src));
}
__device__ __forceinline__ void cp_commit() { asm volatile("cp.async.commit_group;\n" ::); }
__device__ __forceinline__ void cp_wait3()  { asm volatile("cp.async.wait_group 3;\n" ::); }
__device__ __forceinline__ void cp_wait2()  { asm volatile("cp.async.wait_group 2;\n" ::); }
__device__ __forceinline__ void cp_wait1()  { asm volatile("cp.async.wait_group 1;\n" ::); }
__device__ __forceinline__ void cp_wait0()  { asm volatile("cp.async.wait_group 0;\n" ::); }

// ===========================================================================
// Pass A: attention.  Block = (h, 32-pixel w-tile), 256 threads.
// Stages the full 32-channel ref tile, computes softmax attention, stores attG.
// ===========================================================================
#define A_TW   32
#define A_ROW  (A_TW*S_)     // 288 floats per channel row
#define A_F4R  (A_ROW/4)     // 72
#define A_TF4  (C_*A_F4R)    // 2304 float4
#define A_OFFR 0
#define A_OFFW (C_*A_ROW)          // WpT[c*32+d] : 1024
#define A_OFFB (A_OFFW+1024)       // bp : 32
#define A_OFFP (A_OFFB+32)         // pc4[d*32+w] : 1024
#define A_OFFU (A_OFFP+1024)       // u[c*32+w]   : 1024
#define A_SMEMF (A_OFFU+1024)      // 12320 floats
#define A_SMEMB (A_SMEMF*4)        // 49280 B

__global__ __launch_bounds__(256)
void attn_kernel(const float* __restrict__ f,
                 const float* __restrict__ Wp,
                 const float* __restrict__ bp) {
    extern __shared__ float sm[];
    float* refS = sm + A_OFFR;
    float* WpT  = sm + A_OFFW;
    float* bpS  = sm + A_OFFB;
    float* pc4  = sm + A_OFFP;
    float* uS   = sm + A_OFFU;

    const int t  = threadIdx.x;
    const int h  = blockIdx.y;
    const int w0 = blockIdx.x * A_TW;

    const float4* fb4 = (const float4*)f;
    const size_t tile4 = ((size_t)h * WS + (size_t)w0 * S_) >> 2;

    // stage ref tile: 2304 f4 = 9 rounds of 256
    #pragma unroll
    for (int i = 0; i < 9; i++) {
        int j = t + i * 256;
        int c = j / A_F4R;
        int k = j - c * A_F4R;
        cp16(refS + c * A_ROW + k * 4, fb4 + (size_t)c * HWS4 + tile4 + k);
    }
    cp_commit();

    for (int i = t; i < C_ * C_; i += 256) {
        int d = i >> 5, c = i & 31;
        WpT[c * 32 + d] = Wp[i];
    }
    if (t < C_) bpS[t] = bp[t];

    cp_wait0();
    __syncthreads();

    // pc4[d][w] = sum_c Wp[d,c]*ref[c,w,4] + bp[d]   (1024 items)
    #pragma unroll
    for (int i = 0; i < 4; i++) {
        int item = t + i * 256;
        int w = item & 31, d = item >> 5;
        float acc = bpS[d];
        #pragma unroll
        for (int c = 0; c < C_; c++)
            acc += WpT[c * 32 + d] * refS[c * A_ROW + w * S_ + 4];
        pc4[d * 32 + w] = acc;
    }
    __syncthreads();

    // u[c][w] = sum_d pc4[d][w]*Wp[d,c]
    #pragma unroll
    for (int i = 0; i < 4; i++) {
        int item = t + i * 256;
        int w = item & 31, c = item >> 5;
        float acc = 0.f;
        #pragma unroll
        for (int d = 0; d < C_; d++)
            acc += pc4[d * 32 + w] * WpT[c * 32 + d];
        uS[c * 32 + w] = acc;
    }
    __syncthreads();

    // logits + softmax, one pixel per lane (t<32), store att to gmem
    if (t < A_TW) {
        const int w = t;
        float v = 0.f;
        #pragma unroll
        for (int d = 0; d < C_; d++) v += pc4[d * 32 + w] * bpS[d];

        float lg[S_];
        #pragma unroll
        for (int s = 0; s < S_; s++) {
            float a = v;
            #pragma unroll
            for (int c = 0; c < C_; c++)
                a += uS[c * 32 + w] * refS[c * A_ROW + w * S_ + s];
            lg[s] = a * 0.17677669529663687f;   // 1/sqrt(32)
        }
        float mx = lg[0];
        #pragma unroll
        for (int s = 1; s < S_; s++) mx = fmaxf(mx, lg[s]);
        float sum = 0.f;
        #pragma unroll
        for (int s = 0; s < S_; s++) { lg[s] = expf(lg[s] - mx); sum += lg[s]; }
        float inv = 1.f / sum;
        float* ap = attG + ((size_t)h * W_ + w0 + w) * S_;
        #pragma unroll
        for (int s = 0; s < S_; s++) ap[s] = lg[s] * inv;
    }
}

// ===========================================================================
// Pass B: grouped correlation.  Warp-autonomous pipelines, no block barriers.
// Block = (h, 8-pixel w-tile), 8 warps; warp g handles group g.
// Per-warp smem: 4-slot src ring + 1 ref slot, each 4ch x 72 floats.
// Lane = (c, wl): c = lane>>3 (channel in group), wl = lane&7 (pixel).
// ===========================================================================
#define B_TW   8
#define B_ROW  (B_TW*S_)     // 72 floats per channel row
#define B_F4R  (B_ROW/4)     // 18 f4 per channel row
#define SLOT   292           // 288 data + 4 pad (16B-aligned stride)
#define WSLOTS 5             // 4 ring + 1 ref
#define B_WARPF (WSLOTS*SLOT)        // 1460 floats per warp
#define B_SMEMF (8*B_WARPF)          // 11680
#define B_SMEMB (B_SMEMF*4)          // 46720 B -> 4 blocks/SM

// stage one 4-channel slice (72 f4): lanes issue 2 (+1 for lane<8)
__device__ __forceinline__ void stage_slice(float* dst, const float4* gbase, int lane) {
    #pragma unroll
    for (int i = 0; i < 2; i++) {
        int j = lane + i * 32;           // 0..63
        int c = j / B_F4R;
        int k = j - c * B_F4R;
        cp16(dst + c * B_ROW + k * 4, gbase + (size_t)c * HWS4 + k);
    }
    if (lane < (72 - 64)) {
        int j = lane + 64;               // 64..71
        int c = j / B_F4R;
        int k = j - c * B_F4R;
        cp16(dst + c * B_ROW + k * 4, gbase + (size_t)c * HWS4 + k);
    }
    cp_commit();
}

__global__ __launch_bounds__(256)
void corr_kernel(const float* __restrict__ f,
                 float* __restrict__ out) {
    extern __shared__ float sm[];

    const int t    = threadIdx.x;
    const int lane = t & 31;
    const int wid  = t >> 5;         // = group g
    const int c    = lane >> 3;      // channel within group
    const int wl   = lane & 7;       // pixel within tile
    const int h    = blockIdx.y;
    const int w0   = blockIdx.x * B_TW;

    float* slice = sm + wid * B_WARPF;         // this warp's region
    float* refT  = slice + 4 * SLOT;           // ref slot

    const float4* fb4 = (const float4*)f;
    // warp base: (image, channel-group, h, w0)
    const size_t tile4 = ((size_t)h * WS + (size_t)w0 * S_) >> 2;
    const size_t gch4  = (size_t)(wid * 4) * HWS4 + tile4;

    // prologue: ref (g0), src0..2 (g1..g3)
    stage_slice(refT,            fb4 + gch4, lane);                       // image 0
    stage_slice(slice + 0*SLOT,  fb4 + (size_t)1*CHWS4 + gch4, lane);     // src0
    stage_slice(slice + 1*SLOT,  fb4 + (size_t)2*CHWS4 + gch4, lane);     // src1
    stage_slice(slice + 2*SLOT,  fb4 + (size_t)3*CHWS4 + gch4, lane);     // src2

    // attention row for this pixel (broadcast across the 4 c-lanes; L2-hot)
    const float* ap = attG + ((size_t)h * W_ + w0 + wl) * S_;
    float att_r[S_];
    #pragma unroll
    for (int s = 0; s < S_; s++) att_r[s] = ap[s];

    cp_wait3();          // ref slice complete (3 src groups pending)

    float ra[S_];
    #pragma unroll
    for (int s = 0; s < S_; s++)
        ra[s] = refT[c * B_ROW + wl * S_ + s] * att_r[s];

    const size_t outBase = (size_t)h * W_ + w0 + wl;

    // warp-autonomous main loop: no block barriers anywhere
    #pragma unroll 1
    for (int n = 0; n < NSRC; n++) {
        if (n <= 5) cp_wait2();      // src n complete (2 later groups pending)
        else if (n == 6) cp_wait1();
        else cp_wait0();

        const float* sb = slice + (n & 3) * SLOT + c * B_ROW + wl * S_;
        float acc = 0.f;
        #pragma unroll
        for (int s = 0; s < S_; s++)
            acc += ra[s] * sb[s];

        acc += __shfl_xor_sync(0xFFFFFFFFu, acc, 8);
        acc += __shfl_xor_sync(0xFFFFFFFFu, acc, 16);
        if (c == 0)
            out[((size_t)(n * G_ + wid)) * (H_ * W_) + outBase] = acc;

        // refill slot (n+3)&3 (consumed in iter n-1) with src n+3 = image n+4
        if (n <= 4)
            stage_slice(slice + ((n + 3) & 3) * SLOT,
                        fb4 + (size_t)(n + 4) * CHWS4 + gch4, lane);
    }
}

// ===========================================================================
extern "C" void kernel_launch(void* const* d_in, const int* in_sizes, int n_in,
                              void* d_out, int out_size) {
    const float* f  = (const float*)d_in[0];
    const float* Wp = (const float*)d_in[1];
    const float* bp = (const float*)d_in[2];
    float* out = (float*)d_out;

    cudaFuncSetAttribute(attn_kernel,
                         cudaFuncAttributeMaxDynamicSharedMemorySize, A_SMEMB);
    cudaFuncSetAttribute(corr_kernel,
                         cudaFuncAttributeMaxDynamicSharedMemorySize, B_SMEMB);

    dim3 gridA(W_ / A_TW, H_);   // (8, 192)
    attn_kernel<<<gridA, 256, A_SMEMB>>>(f, Wp, bp);

    dim3 gridB(W_ / B_TW, H_);   // (32, 192)
    corr_kernel<<<gridB, 256, B_SMEMB>>>(f, out);
}

// round 8
// speedup vs baseline: 1.0143x; 1.0143x over previous
#include <cuda_runtime.h>
#include <cstdint>

// Problem constants
#define C_    32
#define S_    9
#define H_    192
#define W_    256
#define G_    8
#define NSRC  8

#define WS    (W_*S_)        // 2304
#define HWS   (H_*WS)        // 442368
#define CHWS  (C_*HWS)       // 14155776
#define HWS4  (HWS>>2)       // 110592
#define CHWS4 (CHWS>>2)      // 3538944

// ---------------------------------------------------------------------------
// cp.async helpers
// ---------------------------------------------------------------------------
__device__ __forceinline__ void cp16(float* dst, const float4* src) {
    uint32_t s = (uint32_t)__cvta_generic_to_shared(dst);
    asm volatile("cp.async.cg.shared.global [%0], [%1], 16;\n" :: "r"(s), "l"(src));
}
__device__ __forceinline__ void cp_commit() { asm volatile("cp.async.commit_group;\n" ::); }
__device__ __forceinline__ void cp_wait3()  { asm volatile("cp.async.wait_group 3;\n" ::); }
__device__ __forceinline__ void cp_wait2()  { asm volatile("cp.async.wait_group 2;\n" ::); }
__device__ __forceinline__ void cp_wait1()  { asm volatile("cp.async.wait_group 1;\n" ::); }
__device__ __forceinline__ void cp_wait0()  { asm volatile("cp.async.wait_group 0;\n" ::); }

// ===========================================================================
// Fused kernel. Block = (h, 8-pixel w-tile), 8 warps; warp g = channel group g.
// Per-warp smem: 4-slot src ring + 1 ref slot, each 4ch x 72 floats.
// Lane = (c, wl): c = lane>>3 (channel in group), wl = lane&7 (pixel).
// Prologue computes softmax attention cooperatively (all 32 channels live
// across the block's 8 warps). Main loop is warp-autonomous streaming.
// ===========================================================================
#define B_TW   8
#define B_ROW  (B_TW*S_)     // 72 floats per channel row
#define B_F4R  (B_ROW/4)     // 18 f4 per channel row
#define SLOT   292           // 288 data + 4 pad
#define WSLOTS 5             // 4 ring + 1 ref
#define B_WARPF (WSLOTS*SLOT)        // 1460 floats per warp
#define RING_F  (8*B_WARPF)          // 11680 floats

// block-shared scratch after the ring region
#define OFF_WPT  RING_F              // WpT[c*33+d] : 1056  (stride-33: conflict-free)
#define OFF_BP   (OFF_WPT+1056)      // 32
#define OFF_PC4  (OFF_BP+32)         // pc4[w*33+d] : 264   (stride-33)
#define OFF_LGP  (OFF_PC4+264)       // lgPart[g*72+w*9+s] : 576
#define OFF_ATT  (OFF_LGP+576)       // att[w*9+s] : 72
#define SMEM_FLOATS (OFF_ATT+72)     // 13680
#define SMEM_BYTES  (SMEM_FLOATS*4)  // 54720 B -> 4 blocks/SM

// stage one 4-channel slice (72 f4): lanes issue 2 (+1 for lane<8)
__device__ __forceinline__ void stage_slice(float* dst, const float4* gbase, int lane) {
    #pragma unroll
    for (int i = 0; i < 2; i++) {
        int j = lane + i * 32;           // 0..63
        int c = j / B_F4R;
        int k = j - c * B_F4R;
        cp16(dst + c * B_ROW + k * 4, gbase + (size_t)c * HWS4 + k);
    }
    if (lane < (72 - 64)) {
        int j = lane + 64;               // 64..71
        int c = j / B_F4R;
        int k = j - c * B_F4R;
        cp16(dst + c * B_ROW + k * 4, gbase + (size_t)c * HWS4 + k);
    }
    cp_commit();
}

__global__ __launch_bounds__(256)
void gcfs_fused(const float* __restrict__ f,
                const float* __restrict__ Wp,
                const float* __restrict__ bp,
                float* __restrict__ out) {
    extern __shared__ float sm[];
    float* WpT  = sm + OFF_WPT;
    float* bpS  = sm + OFF_BP;
    float* pc4  = sm + OFF_PC4;
    float* lgP  = sm + OFF_LGP;
    float* attS = sm + OFF_ATT;

    const int t    = threadIdx.x;
    const int lane = t & 31;
    const int wid  = t >> 5;         // = group g
    const int c    = lane >> 3;      // channel within group
    const int wl   = lane & 7;       // pixel within tile
    const int h    = blockIdx.y;
    const int w0   = blockIdx.x * B_TW;

    float* slice = sm + wid * B_WARPF;         // this warp's ring region
    float* refT  = slice + 4 * SLOT;           // ref slot

    const float4* fb4 = (const float4*)f;
    const size_t tile4 = ((size_t)h * WS + (size_t)w0 * S_) >> 2;
    const size_t gch4  = (size_t)(wid * 4) * HWS4 + tile4;

    // --- prologue staging: ref (g0), src0..2 (g1..g3), per-warp ---
    stage_slice(refT,            fb4 + gch4, lane);                       // image 0
    stage_slice(slice + 0*SLOT,  fb4 + (size_t)1*CHWS4 + gch4, lane);     // src0
    stage_slice(slice + 1*SLOT,  fb4 + (size_t)2*CHWS4 + gch4, lane);     // src1
    stage_slice(slice + 2*SLOT,  fb4 + (size_t)3*CHWS4 + gch4, lane);     // src2

    // Wp transposed (stride 33) + bp + pc4 init (L2-hot plain loads)
    for (int i = t; i < C_ * C_; i += 256) {
        int d = i >> 5, cc = i & 31;
        WpT[cc * 33 + d] = Wp[i];
    }
    if (t < C_) bpS[t] = bp[t];
    {   // pc4[w*33+d] = bp[d]
        int w = t >> 5, d = t & 31;
        pc4[w * 33 + d] = bp[d];
    }

    cp_wait3();          // own ref slice complete (src0..2 pending)
    __syncthreads();     // ref of ALL warps + WpT + pc4 init visible

    // --- partial pc4: warp g adds its 4-channel contribution ---
    // lane d(0..31): for each w: sum_{cl} Wp[d, 4g+cl] * ref[cl, w, 4]
    {
        const int d = lane;
        #pragma unroll
        for (int w = 0; w < B_TW; w++) {
            float acc = 0.f;
            #pragma unroll
            for (int cl = 0; cl < 4; cl++)
                acc += WpT[(wid * 4 + cl) * 33 + d] * refT[cl * B_ROW + w * S_ + 4];
            atomicAdd(&pc4[w * 33 + d], acc);
        }
    }
    __syncthreads();

    // --- u in registers + logit partials ---
    // lane (c,wl): u = sum_d pc4[wl][d] * Wp[d, c0+c]
    {
        float u = 0.f;
        #pragma unroll
        for (int d = 0; d < C_; d++)
            u += pc4[wl * 33 + d] * WpT[(wid * 4 + c) * 33 + d];

        // partial logits over this lane's channel: t[s] = u * ref[c,wl,s]
        #pragma unroll
        for (int s = 0; s < S_; s++) {
            float v = u * refT[c * B_ROW + wl * S_ + s];
            v += __shfl_xor_sync(0xFFFFFFFFu, v, 8);
            v += __shfl_xor_sync(0xFFFFFFFFu, v, 16);
            if (c == 0) lgP[wid * 72 + wl * S_ + s] = v;   // lanes 0..7
        }
    }
    __syncthreads();

    // --- final logits + softmax: 8 threads, one pixel each ---
    if (t < B_TW) {
        const int w = t;
        float v = 0.f;
        #pragma unroll
        for (int d = 0; d < C_; d++) v += pc4[w * 33 + d] * bpS[d];

        float lg[S_];
        #pragma unroll
        for (int s = 0; s < S_; s++) {
            float a = v;
            #pragma unroll
            for (int g = 0; g < G_; g++)
                a += lgP[g * 72 + w * S_ + s];
            lg[s] = a * 0.17677669529663687f;   // 1/sqrt(32)
        }
        float mx = lg[0];
        #pragma unroll
        for (int s = 1; s < S_; s++) mx = fmaxf(mx, lg[s]);
        float sum = 0.f;
        #pragma unroll
        for (int s = 0; s < S_; s++) { lg[s] = expf(lg[s] - mx); sum += lg[s]; }
        float inv = 1.f / sum;
        #pragma unroll
        for (int s = 0; s < S_; s++) attS[w * S_ + s] = lg[s] * inv;
    }
    __syncthreads();

    // --- ra = ref * att in registers ---
    float ra[S_];
    #pragma unroll
    for (int s = 0; s < S_; s++)
        ra[s] = refT[c * B_ROW + wl * S_ + s] * attS[wl * S_ + s];

    const size_t outBase = (size_t)h * W_ + w0 + wl;

    // --- warp-autonomous main loop: no block barriers ---
    #pragma unroll 1
    for (int n = 0; n < NSRC; n++) {
        if (n <= 5) cp_wait2();      // src n complete (2 later groups pending)
        else if (n == 6) cp_wait1();
        else cp_wait0();

        const float* sb = slice + (n & 3) * SLOT + c * B_ROW + wl * S_;
        float acc = 0.f;
        #pragma unroll
        for (int s = 0; s < S_; s++)
            acc += ra[s] * sb[s];

        acc += __shfl_xor_sync(0xFFFFFFFFu, acc, 8);
        acc += __shfl_xor_sync(0xFFFFFFFFu, acc, 16);
        if (c == 0)
            out[((size_t)(n * G_ + wid)) * (H_ * W_) + outBase] = acc;

        // refill slot (n+3)&3 with src n+3 = image n+4
        if (n <= 4)
            stage_slice(slice + ((n + 3) & 3) * SLOT,
                        fb4 + (size_t)(n + 4) * CHWS4 + gch4, lane);
    }
}

// ===========================================================================
extern "C" void kernel_launch(void* const* d_in, const int* in_sizes, int n_in,
                              void* d_out, int out_size) {
    const float* f  = (const float*)d_in[0];
    const float* Wp = (const float*)d_in[1];
    const float* bp = (const float*)d_in[2];
    float* out = (float*)d_out;

    cudaFuncSetAttribute(gcfs_fused,
                         cudaFuncAttributeMaxDynamicSharedMemorySize, SMEM_BYTES);
    dim3 grid(W_ / B_TW, H_);   // (32, 192)
    gcfs_fused<<<grid, 256, SMEM_BYTES>>>(f, Wp, bp, out);
}

// round 9
// speedup vs baseline: 1.0592x; 1.0442x over previous
#include <cuda_runtime.h>
#include <cstdint>

// Problem constants
#define C_    32
#define S_    9
#define H_    192
#define W_    256
#define G_    8
#define NSRC  8

#define WS    (W_*S_)        // 2304
#define HWS   (H_*WS)        // 442368
#define CHWS  (C_*HWS)       // 14155776
#define HWS4  (HWS>>2)       // 110592
#define CHWS4 (CHWS>>2)      // 3538944

// attention scratch + precomputed Gram matrix
__device__ float attG[H_ * W_ * S_];
__device__ float MG[C_ * C_];   // M[c][d] = sum_k Wp[k,c]*Wp[k,d]
__device__ float qG[C_];        // q[c]    = sum_k Wp[k,c]*bp[k]
__device__ float c0G;           // bp.bp

// ---------------------------------------------------------------------------
// cp.async helpers
// ---------------------------------------------------------------------------
__device__ __forceinline__ void cp16(float* dst, const float4* src) {
    uint32_t s = (uint32_t)__cvta_generic_to_shared(dst);
    asm volatile("cp.async.cg.shared.global [%0], [%1], 16;\n" :: "r"(s), "l"(src));
}
__device__ __forceinline__ void cp_commit() { asm volatile("cp.async.commit_group;\n" ::); }
__device__ __forceinline__ void cp_wait3()  { asm volatile("cp.async.wait_group 3;\n" ::); }
__device__ __forceinline__ void cp_wait2()  { asm volatile("cp.async.wait_group 2;\n" ::); }
__device__ __forceinline__ void cp_wait1()  { asm volatile("cp.async.wait_group 1;\n" ::); }
__device__ __forceinline__ void cp_wait0()  { asm volatile("cp.async.wait_group 0;\n" ::); }

// ===========================================================================
// Setup: M = Wp^T Wp, q = Wp^T bp, c0 = bp.bp    (8 blocks x 128 threads)
// ===========================================================================
__global__ void setup_kernel(const float* __restrict__ Wp,
                             const float* __restrict__ bp) {
    const int t = threadIdx.x;
    const int c = blockIdx.x * 4 + (t >> 5);
    const int d = t & 31;
    float acc = 0.f;
    #pragma unroll
    for (int k = 0; k < C_; k++)
        acc += Wp[k * C_ + c] * Wp[k * C_ + d];
    MG[c * C_ + d] = acc;

    if (blockIdx.x == 0 && t < C_) {
        float q = 0.f;
        #pragma unroll
        for (int k = 0; k < C_; k++)
            q += Wp[k * C_ + t] * bp[k];
        qG[t] = q;
    }
    if (blockIdx.x == 0 && t == 0) {
        float s = 0.f;
        #pragma unroll
        for (int k = 0; k < C_; k++) s += bp[k] * bp[k];
        c0G = s;
    }
}

// ===========================================================================
// Pass A: attention via Gram trick.  Block = (h, 16-pixel tile), 128 threads.
// logits[w,s] = u'_w . r_s + k_w ;  u'_w = M r4_w + q ;  k_w = q.r4_w + c0
// ===========================================================================
#define A_TW   16
#define A_ROW  (A_TW*S_)      // 144
#define A_F4R  (A_ROW/4)      // 36
#define A_TF4  (C_*A_F4R)     // 1152 float4
#define A_OFFR 0
#define A_OFFM (C_*A_ROW)           // MS[c*33+d] : 1056
#define A_OFFQ (A_OFFM+1056)        // qS : 32
#define A_OFFU (A_OFFQ+32)          // uS[w*33+c] : 528
#define A_OFFK (A_OFFU+528)         // kS[w] : 16
#define A_OFFL (A_OFFK+16)          // lgS[w*9+s] : 144
#define A_SMEMF (A_OFFL+144)        // 6384 floats
#define A_SMEMB (A_SMEMF*4)         // 25536 B -> ~8 blocks/SM

__global__ __launch_bounds__(128)
void attn_kernel(const float* __restrict__ f) {
    extern __shared__ float sm[];
    float* refS = sm + A_OFFR;
    float* MS   = sm + A_OFFM;
    float* qS   = sm + A_OFFQ;
    float* uS   = sm + A_OFFU;
    float* kS   = sm + A_OFFK;
    float* lgS  = sm + A_OFFL;

    const int t  = threadIdx.x;
    const int h  = blockIdx.y;
    const int w0 = blockIdx.x * A_TW;

    const float4* fb4 = (const float4*)f;
    const size_t tile4 = ((size_t)h * WS + (size_t)w0 * S_) >> 2;

    // stage ref tile: 1152 f4 = 9 rounds of 128
    #pragma unroll
    for (int i = 0; i < 9; i++) {
        int j = t + i * 128;
        int c = j / A_F4R;
        int k = j - c * A_F4R;
        cp16(refS + c * A_ROW + k * 4, fb4 + (size_t)c * HWS4 + tile4 + k);
    }
    cp_commit();

    // M (stride-33) + q  (L2-hot)
    for (int i = t; i < C_ * C_; i += 128) {
        int c = i >> 5, d = i & 31;
        MS[c * 33 + d] = MG[i];
    }
    if (t < C_) qS[t] = qG[t];

    cp_wait0();
    __syncthreads();

    // --- u'[w][c] = sum_d M[c][d]*ref[d,w,4] + q[c] ---
    // warp wq handles pixels 4wq..4wq+3; lane = c; M row cached in regs via loop
    {
        const int c  = t & 31;
        const int wq = t >> 5;
        float acc0 = qS[c], acc1 = qS[c], acc2 = qS[c], acc3 = qS[c];
        #pragma unroll
        for (int d = 0; d < C_; d++) {
            float m = MS[c * 33 + d];                       // conflict-free
            acc0 += m * refS[d * A_ROW + (wq*4+0) * S_ + 4];  // warp-uniform bcast
            acc1 += m * refS[d * A_ROW + (wq*4+1) * S_ + 4];
            acc2 += m * refS[d * A_ROW + (wq*4+2) * S_ + 4];
            acc3 += m * refS[d * A_ROW + (wq*4+3) * S_ + 4];
        }
        uS[(wq*4+0) * 33 + c] = acc0;
        uS[(wq*4+1) * 33 + c] = acc1;
        uS[(wq*4+2) * 33 + c] = acc2;
        uS[(wq*4+3) * 33 + c] = acc3;
    }
    // k_w = q . r4_w + c0   (16 threads)
    if (t < A_TW) {
        float kk = c0G;
        #pragma unroll
        for (int c = 0; c < C_; c++)
            kk += qS[c] * refS[c * A_ROW + t * S_ + 4];
        kS[t] = kk;
    }
    __syncthreads();

    // --- logits: 144 items (w,s) over 128 threads ---
    #pragma unroll
    for (int r = 0; r < 2; r++) {
        int item = t + r * 128;
        if (item < A_TW * S_) {
            int w = item / S_, s = item - w * S_;
            float lg = kS[w];
            #pragma unroll
            for (int c = 0; c < C_; c++)
                lg += uS[w * 33 + c] * refS[c * A_ROW + w * S_ + s];
            lgS[item] = lg * 0.17677669529663687f;   // 1/sqrt(32)
        }
    }
    __syncthreads();

    // --- softmax: 16 threads, one pixel each; write attG ---
    if (t < A_TW) {
        const int w = t;
        float lg[S_];
        #pragma unroll
        for (int s = 0; s < S_; s++) lg[s] = lgS[w * S_ + s];
        float mx = lg[0];
        #pragma unroll
        for (int s = 1; s < S_; s++) mx = fmaxf(mx, lg[s]);
        float sum = 0.f;
        #pragma unroll
        for (int s = 0; s < S_; s++) { lg[s] = expf(lg[s] - mx); sum += lg[s]; }
        float inv = 1.f / sum;
        float* ap = attG + ((size_t)h * W_ + w0 + w) * S_;
        #pragma unroll
        for (int s = 0; s < S_; s++) ap[s] = lg[s] * inv;
    }
}

// ===========================================================================
// Pass B: grouped correlation — UNCHANGED from measured 84.9us version.
// Warp-autonomous pipelines, no block barriers.
// ===========================================================================
#define B_TW   8
#define B_ROW  (B_TW*S_)     // 72
#define B_F4R  (B_ROW/4)     // 18
#define SLOT   292
#define WSLOTS 5
#define B_WARPF (WSLOTS*SLOT)        // 1460
#define B_SMEMF (8*B_WARPF)          // 11680
#define B_SMEMB (B_SMEMF*4)          // 46720 B -> 4 blocks/SM

__device__ __forceinline__ void stage_slice(float* dst, const float4* gbase, int lane) {
    #pragma unroll
    for (int i = 0; i < 2; i++) {
        int j = lane + i * 32;
        int c = j / B_F4R;
        int k = j - c * B_F4R;
        cp16(dst + c * B_ROW + k * 4, gbase + (size_t)c * HWS4 + k);
    }
    if (lane < (72 - 64)) {
        int j = lane + 64;
        int c = j / B_F4R;
        int k = j - c * B_F4R;
        cp16(dst + c * B_ROW + k * 4, gbase + (size_t)c * HWS4 + k);
    }
    cp_commit();
}

__global__ __launch_bounds__(256)
void corr_kernel(const float* __restrict__ f,
                 float* __restrict__ out) {
    extern __shared__ float sm[];

    const int t    = threadIdx.x;
    const int lane = t & 31;
    const int wid  = t >> 5;
    const int c    = lane >> 3;
    const int wl   = lane & 7;
    const int h    = blockIdx.y;
    const int w0   = blockIdx.x * B_TW;

    float* slice = sm + wid * B_WARPF;
    float* refT  = slice + 4 * SLOT;

    const float4* fb4 = (const float4*)f;
    const size_t tile4 = ((size_t)h * WS + (size_t)w0 * S_) >> 2;
    const size_t gch4  = (size_t)(wid * 4) * HWS4 + tile4;

    stage_slice(refT,            fb4 + gch4, lane);
    stage_slice(slice + 0*SLOT,  fb4 + (size_t)1*CHWS4 + gch4, lane);
    stage_slice(slice + 1*SLOT,  fb4 + (size_t)2*CHWS4 + gch4, lane);
    stage_slice(slice + 2*SLOT,  fb4 + (size_t)3*CHWS4 + gch4, lane);

    const float* ap = attG + ((size_t)h * W_ + w0 + wl) * S_;
    float att_r[S_];
    #pragma unroll
    for (int s = 0; s < S_; s++) att_r[s] = ap[s];

    cp_wait3();

    float ra[S_];
    #pragma unroll
    for (int s = 0; s < S_; s++)
        ra[s] = refT[c * B_ROW + wl * S_ + s] * att_r[s];

    const size_t outBase = (size_t)h * W_ + w0 + wl;

    #pragma unroll 1
    for (int n = 0; n < NSRC; n++) {
        if (n <= 5) cp_wait2();
        else if (n == 6) cp_wait1();
        else cp_wait0();

        const float* sb = slice + (n & 3) * SLOT + c * B_ROW + wl * S_;
        float acc = 0.f;
        #pragma unroll
        for (int s = 0; s < S_; s++)
            acc += ra[s] * sb[s];

        acc += __shfl_xor_sync(0xFFFFFFFFu, acc, 8);
        acc += __shfl_xor_sync(0xFFFFFFFFu, acc, 16);
        if (c == 0)
            out[((size_t)(n * G_ + wid)) * (H_ * W_) + outBase] = acc;

        if (n <= 4)
            stage_slice(slice + ((n + 3) & 3) * SLOT,
                        fb4 + (size_t)(n + 4) * CHWS4 + gch4, lane);
    }
}

// ===========================================================================
extern "C" void kernel_launch(void* const* d_in, const int* in_sizes, int n_in,
                              void* d_out, int out_size) {
    const float* f  = (const float*)d_in[0];
    const float* Wp = (const float*)d_in[1];
    const float* bp = (const float*)d_in[2];
    float* out = (float*)d_out;

    cudaFuncSetAttribute(attn_kernel,
                         cudaFuncAttributeMaxDynamicSharedMemorySize, A_SMEMB);
    cudaFuncSetAttribute(corr_kernel,
                         cudaFuncAttributeMaxDynamicSharedMemorySize, B_SMEMB);

    setup_kernel<<<8, 128>>>(Wp, bp);

    dim3 gridA(W_ / A_TW, H_);   // (16, 192)
    attn_kernel<<<gridA, 128, A_SMEMB>>>(f);

    dim3 gridB(W_ / B_TW, H_);   // (32, 192)
    corr_kernel<<<gridB, 256, B_SMEMB>>>(f, out);
}

// round 10
// speedup vs baseline: 1.1666x; 1.1014x over previous
#include <cuda_runtime.h>
#include <cstdint>

// Problem constants
#define C_    32
#define S_    9
#define H_    192
#define W_    256
#define G_    8
#define NSRC  8

#define WS    (W_*S_)        // 2304
#define HWS   (H_*WS)        // 442368
#define CHWS  (C_*HWS)       // 14155776
#define HWS4  (HWS>>2)       // 110592
#define CHWS4 (CHWS>>2)      // 3538944

// ===========================================================================
// Fused single kernel.
// Warp tile = 4 pixels x 32 channels. Block = 4 warps = 16 pixels.
// Each warp: stages its own tiles (ref + depth-2 src ring), computes softmax
// attention warp-locally, then streams 8 src images warp-autonomously.
// Only ONE __syncthreads in the kernel (Wp smem visibility).
// Lane map: px = lane>>3 (pixel 0..3), q8 = lane&7.
// ===========================================================================
#define WPX   4
#define NW    4
#define B_TW  (WPX*NW)       // 16 pixels per block
#define CROW  36             // floats per channel per warp tile (4 px * 9)
#define SLOT  (C_*CROW)      // 1152 floats
#define WARPF (3*SLOT)       // slot0, slot1, ref

#define OFF_WPD (NW*WARPF)           // WpD[d*33+c] : 1056
#define OFF_BP  (OFF_WPD+1056)       // 32
#define OFF_PSC (OFF_BP+32)          // per-warp p4 transpose scratch: 4*136
#define SMEM_FLOATS (OFF_PSC + NW*136)   // 15456
#define SMEM_BYTES  (SMEM_FLOATS*4)      // 61824 B -> 3 blocks/SM

__device__ __forceinline__ void cp16(float* dst, const float4* src) {
    uint32_t s = (uint32_t)__cvta_generic_to_shared(dst);
    asm volatile("cp.async.cg.shared.global [%0], [%1], 16;\n" :: "r"(s), "l"(src));
}
__device__ __forceinline__ void cp_commit() { asm volatile("cp.async.commit_group;\n" ::); }
__device__ __forceinline__ void cp_wait2()  { asm volatile("cp.async.wait_group 2;\n" ::); }
__device__ __forceinline__ void cp_wait1()  { asm volatile("cp.async.wait_group 1;\n" ::); }
__device__ __forceinline__ void cp_wait0()  { asm volatile("cp.async.wait_group 0;\n" ::); }

// Stage one warp tile: 288 float4 (32 ch x 9 f4), 9 per lane, linear smem.
__device__ __forceinline__ void stage_tile(float* dst, const float4* gbase, int lane) {
    #pragma unroll
    for (int i = 0; i < 9; i++) {
        int j = lane + 32 * i;           // 0..287
        int c = j / 9;
        int k = j - c * 9;
        cp16(dst + j * 4, gbase + (size_t)c * HWS4 + k);
    }
    cp_commit();
}

__global__ __launch_bounds__(128)
void gcfs_fused(const float* __restrict__ f,
                const float* __restrict__ Wp,
                const float* __restrict__ bp,
                float* __restrict__ out) {
    extern __shared__ float sm[];
    float* WpD = sm + OFF_WPD;       // WpD[d*33+c]
    float* bpS = sm + OFF_BP;

    const int t    = threadIdx.x;
    const int lane = t & 31;
    const int wid  = t >> 5;
    const int px   = lane >> 3;
    const int q8   = lane & 7;
    const int h    = blockIdx.y;
    const int wp0  = blockIdx.x * B_TW + wid * WPX;   // warp's first pixel

    float* warpS = sm + wid * WARPF;
    float* slot0 = warpS;
    float* slot1 = warpS + SLOT;
    float* refS  = warpS + 2 * SLOT;
    float* psc   = sm + OFF_PSC + wid * 136;

    const float4* fb4 = (const float4*)f;
    const size_t base4 = ((size_t)h * WS + (size_t)wp0 * S_) >> 2;  // wp0%4==0

    // --- prologue staging: ref (g0), src0 (g1), src1 (g2) ---
    stage_tile(refS,  fb4 + base4, lane);                        // image 0
    stage_tile(slot0, fb4 + (size_t)1 * CHWS4 + base4, lane);    // image 1
    stage_tile(slot1, fb4 + (size_t)2 * CHWS4 + base4, lane);    // image 2

    // Wp (stride-33) + bp, L2-hot plain loads
    for (int i = t; i < C_ * C_; i += 128) {
        int d = i >> 5, c = i & 31;
        WpD[d * 33 + c] = Wp[i];
    }
    if (t < C_) bpS[t] = bp[t];

    cp_wait2();          // own ref complete; src0/src1 still streaming
    __syncthreads();     // WpD/bp visible (the ONLY block barrier)

    // ===== warp-local attention for this warp's 4 pixels =====
    // Stage 1: p4[px][d] = sum_c Wp[d,c]*ref[c,px,4] + bp[d]; lane holds d=8co+q8
    float p4[4];
    #pragma unroll
    for (int co = 0; co < 4; co++) p4[co] = bpS[co * 8 + q8];
    #pragma unroll
    for (int c = 0; c < C_; c++) {
        float rc = refS[c * CROW + px * S_ + 4];       // multicast (4 addrs, distinct banks)
        #pragma unroll
        for (int co = 0; co < 4; co++)
            p4[co] += WpD[(co * 8 + q8) * 33 + c] * rc;
    }

    // k[px] = p4 . bp  (octet reduce)
    float kk = 0.f;
    #pragma unroll
    for (int co = 0; co < 4; co++) kk += p4[co] * bpS[co * 8 + q8];
    kk += __shfl_xor_sync(0xFFFFFFFFu, kk, 1);
    kk += __shfl_xor_sync(0xFFFFFFFFu, kk, 2);
    kk += __shfl_xor_sync(0xFFFFFFFFu, kk, 4);

    // transpose p4 through per-warp scratch
    #pragma unroll
    for (int co = 0; co < 4; co++)
        psc[px * 33 + co * 8 + q8] = p4[co];
    __syncwarp();

    // Stage 2: u'[px][c] = sum_d Wp[d,c]*p4[px][d]; lane holds c=8co+q8
    float u[4] = {0.f, 0.f, 0.f, 0.f};
    #pragma unroll
    for (int d = 0; d < C_; d++) {
        float pd = psc[px * 33 + d];                   // multicast
        #pragma unroll
        for (int co = 0; co < 4; co++)
            u[co] += WpD[d * 33 + co * 8 + q8] * pd;
    }

    // Stage 3: logits + softmax (redundant across octet lanes)
    float lg[S_];
    #pragma unroll
    for (int s = 0; s < S_; s++) {
        float part = 0.f;
        #pragma unroll
        for (int co = 0; co < 4; co++)
            part += u[co] * refS[(co * 8 + q8) * CROW + px * S_ + s];
        part += __shfl_xor_sync(0xFFFFFFFFu, part, 1);
        part += __shfl_xor_sync(0xFFFFFFFFu, part, 2);
        part += __shfl_xor_sync(0xFFFFFFFFu, part, 4);
        lg[s] = (part + kk) * 0.17677669529663687f;    // 1/sqrt(32)
    }
    float mx = lg[0];
    #pragma unroll
    for (int s = 1; s < S_; s++) mx = fmaxf(mx, lg[s]);
    float sum = 0.f;
    #pragma unroll
    for (int s = 0; s < S_; s++) { lg[s] = expf(lg[s] - mx); sum += lg[s]; }
    float inv = 1.f / sum;

    // ra[co][s] = ref[8co+q8][px][s] * att[px][s]
    float ra[4][S_];
    #pragma unroll
    for (int co = 0; co < 4; co++) {
        #pragma unroll
        for (int s = 0; s < S_; s++)
            ra[co][s] = refS[(co * 8 + q8) * CROW + px * S_ + s] * (lg[s] * inv);
    }

    // ===== warp-autonomous main loop (no block barriers) =====
    const size_t outPix = (size_t)h * W_ + wp0 + px;
    const int ghalf = q8 >> 2;              // which group within co-pair
    const bool storer = (q8 & 3) == 0;      // lanes q8 in {0,4} store

    #pragma unroll 1
    for (int n = 0; n < NSRC; n++) {
        // groups: ref=0, src k = k+1 (k<=1), refills end of iter m = group m+3
        if (n <= 6) cp_wait1(); else cp_wait0();

        const float* sb = ((n & 1) ? slot1 : slot0) + q8 * CROW + px * S_;
        float acc[4];
        #pragma unroll
        for (int co = 0; co < 4; co++) {
            float a = 0.f;
            #pragma unroll
            for (int s = 0; s < S_; s++)
                a += ra[co][s] * sb[co * 8 * CROW + s];
            acc[co] = a;
        }
        #pragma unroll
        for (int co = 0; co < 4; co++) {
            acc[co] += __shfl_xor_sync(0xFFFFFFFFu, acc[co], 1);
            acc[co] += __shfl_xor_sync(0xFFFFFFFFu, acc[co], 2);
        }
        if (storer) {
            #pragma unroll
            for (int co = 0; co < 4; co++)
                out[((size_t)(n * G_ + 2 * co + ghalf)) * (H_ * W_) + outPix] = acc[co];
        }

        // refill the slot just consumed with src n+2 = image n+3
        if (n <= 5)
            stage_tile((n & 1) ? slot1 : slot0,
                       fb4 + (size_t)(n + 3) * CHWS4 + base4, lane);
    }
}

// ===========================================================================
extern "C" void kernel_launch(void* const* d_in, const int* in_sizes, int n_in,
                              void* d_out, int out_size) {
    const float* f  = (const float*)d_in[0];
    const float* Wp = (const float*)d_in[1];
    const float* bp = (const float*)d_in[2];
    float* out = (float*)d_out;

    cudaFuncSetAttribute(gcfs_fused,
                         cudaFuncAttributeMaxDynamicSharedMemorySize, SMEM_BYTES);
    dim3 grid(W_ / B_TW, H_);   // (16, 192)
    gcfs_fused<<<grid, 128, SMEM_BYTES>>>(f, Wp, bp, out);
}